// round 15
// baseline (speedup 1.0000x reference)
#include <cuda_runtime.h>
#include <cstdint>

// Fixed problem shape: B=16, C=1, H=128, W=8192, NMAX=64
#define BB   16
#define HH   128
#define WW   8192
#define NMX  64
#define ROWS 4                 // rows per pack block -> grid.z = 32
#define BIGV 0x3FFFFFFF

// Scratch (allocation-free rule: device globals)
__device__ int g_map[BB][WW];   // per-column: >=0 src, -1 sep, -2 zero

__device__ __forceinline__ void cp_async4(uint32_t smem_addr, const void* gptr) {
    asm volatile("cp.async.ca.shared.global [%0], [%1], 4;\n"
                 :: "r"(smem_addr), "l"(gptr));
}

// ---------------------------------------------------------------------------
// Kernel 1: fused meta + map. grid = (16 batches, 8 col-chunks), block 256.
// ---------------------------------------------------------------------------
__global__ void __launch_bounds__(256)
map_kernel(const int* __restrict__ xi,
           const int* __restrict__ N,
           float* __restrict__ out_xi,
           int write_xi) {
    const int b = blockIdx.x;
    const int t = threadIdx.x;

    __shared__ int s_start[NMX + 1];
    __shared__ int s_end[NMX];
    __shared__ int s_src[NMX];
    __shared__ int s_n;
    __shared__ int sh_w0;

    if (t == 0) s_n = N[b];
    __syncthreads();
    const int n = s_n;

    if (t < NMX) {
        const int s = xi[(b * NMX + t) * 2 + 0];
        const int e = xi[(b * NMX + t) * 2 + 1];
        const int valid = (t < n) ? 1 : 0;
        const int wv = valid ? max(e - s, 0) : 0;

        int sc = wv;
        #pragma unroll
        for (int off = 1; off < 32; off <<= 1) {
            int v = __shfl_up_sync(0xFFFFFFFFu, sc, off);
            if ((t & 31) >= off) sc += v;
        }
        if (t == 31) sh_w0 = sc;
        __syncwarp();
        s_end[t]   = sc;      // stash partial scan
        s_src[t]   = s;
        s_start[t] = valid;   // stash validity
    }
    __syncthreads();
    if (t < NMX) {
        const int valid = s_start[t];
        const int s = s_src[t];
        const int e = xi[(b * NMX + t) * 2 + 1];
        const int wv = valid ? max(e - s, 0) : 0;
        const int csum = s_end[t] + ((t >= 32) ? sh_w0 : 0);
        const int sn = csum - wv + t;
        const int en = csum + t;
        s_start[t] = valid ? sn : BIGV;
        s_end[t]   = en;
        if (write_xi && blockIdx.y == 0) {
            out_xi[(b * NMX + t) * 2 + 0] = valid ? (float)sn : 0.0f;
            out_xi[(b * NMX + t) * 2 + 1] = valid ? (float)en : 0.0f;
        }
    }
    if (t == 0) s_start[NMX] = BIGV;
    __syncthreads();

    const int j0 = (blockIdx.y * 256 + t) * 4;

    int lo = 0, hi = n;
    while (lo < hi) {
        int mid = (lo + hi) >> 1;
        if (s_start[mid] <= j0) lo = mid + 1; else hi = mid;
    }
    int cur = lo - 1;

    int mv[4];
    #pragma unroll
    for (int c = 0; c < 4; c++) {
        const int j = j0 + c;
        if (j >= s_start[cur + 1]) cur++;     // at most one boundary in 4 cols
        const int s = s_start[cur];
        const int e = s_end[cur];
        int o = -2;                            // zero fill
        if (j < e)                      o = s_src[cur] + (j - s);
        else if (j == e && cur < n - 1) o = -1;  // separator
        mv[c] = o;
    }
    int4 m; m.x = mv[0]; m.y = mv[1]; m.z = mv[2]; m.w = mv[3];
    *reinterpret_cast<int4*>(&g_map[b][j0]) = m;
}

// ---------------------------------------------------------------------------
// Kernel 2: pack with cp.async gather into warp-private smem.
// grid = (WW/1024=8, BB=16, HH/4=32) = 4096 blocks, block 256 = 8 warps.
// Each warp owns a 128-col swath. It issues ALL 16 gather cp.asyncs for its
// 4-row tile (register-free MLP=16), STS-fills sep/zero lanes, waits ONCE,
// then reads back LDS.128 and emits coalesced STG.128.
// ---------------------------------------------------------------------------
__global__ void __launch_bounds__(256)
pack_kernel(const float* __restrict__ x,
            const float* __restrict__ sep_param,
            float* __restrict__ out) {
    const int b    = blockIdx.y;
    const int t    = threadIdx.x;
    const int w    = t >> 5;          // warp 0..7
    const int lane = t & 31;

    __shared__ __align__(16) float s_tile[8][ROWS][128];   // 16 KB

    const int   wcol = blockIdx.x * 1024 + w * 128;
    const float sep  = __ldg(sep_param);

    // Map for my 4 coalesced gather columns (stride 32 within warp swath).
    int   mm[4];
    float fv[4];
    #pragma unroll
    for (int k = 0; k < 4; k++) {
        mm[k] = g_map[b][wcol + lane + 32 * k];
        fv[k] = (mm[k] == -1) ? sep : 0.0f;
    }

    const int h0 = blockIdx.z * ROWS;
    const float* __restrict__ xb = x   + (size_t)b * HH * WW + (size_t)h0 * WW;
    float* __restrict__       ob = out + (size_t)b * HH * WW + (size_t)h0 * WW;

    // ---- Phase A: 16 register-free gathers in flight, one wait ----
    #pragma unroll
    for (int r = 0; r < ROWS; r++) {
        const size_t row = (size_t)r * WW;
        #pragma unroll
        for (int k = 0; k < 4; k++) {
            float* sp = &s_tile[w][r][lane + 32 * k];
            if (mm[k] >= 0) {
                cp_async4((uint32_t)__cvta_generic_to_shared(sp),
                          xb + row + mm[k]);
            } else {
                *sp = fv[k];
            }
        }
    }
    asm volatile("cp.async.commit_group;\n");
    asm volatile("cp.async.wait_group 0;\n");
    __syncwarp();

    // ---- Phase B: float4 from smem -> coalesced STG.128 ----
    #pragma unroll
    for (int r = 0; r < ROWS; r++) {
        const float4 f = *reinterpret_cast<const float4*>(
            &s_tile[w][r][4 * lane]);
        __stcs(reinterpret_cast<float4*>(
            ob + (size_t)r * WW + wcol + 4 * lane), f);
    }
}

// ---------------------------------------------------------------------------
extern "C" void kernel_launch(void* const* d_in, const int* in_sizes, int n_in,
                              void* d_out, int out_size) {
    const float* x   = (const float*)d_in[0];
    const int*   xi  = (const int*)  d_in[1];
    const int*   N   = (const int*)  d_in[2];
    const float* sep = (const float*)d_in[3];
    float*       out = (float*)d_out;

    const long long XN = (long long)BB * HH * WW;   // 16,777,216
    const int write_xi = ((long long)out_size > XN) ? 1 : 0;

    dim3 mgrid(BB, WW / (256 * 4));
    map_kernel<<<mgrid, 256>>>(xi, N, out + XN, write_xi);

    dim3 grid(WW / 1024, BB, HH / ROWS);
    pack_kernel<<<grid, 256>>>(x, sep, out);
}

// round 16
// speedup vs baseline: 1.2640x; 1.2640x over previous
#include <cuda_runtime.h>

// Fixed problem shape: B=16, C=1, H=128, W=8192, NMAX=64
#define BB   16
#define HH   128
#define WW   8192
#define NMX  64
#define ROWS 8                 // rows per block -> grid.z = 16, 2048 blocks
#define BIGV 0x3FFFFFFF

// ---------------------------------------------------------------------------
// SINGLE fused kernel: meta scan + classification + warp-private transpose
// pack. grid = (WW/1024=8, BB=16, HH/8=16) = 2048 blocks, block 256 = 8 warps.
//
// Preamble (per block, ~150 cyc): 64-wide shuffle scan of chirp widths ->
// compressed starts/ends in shared; 4 binary searches per lane classify the
// lane's 4 stride-32 gather columns. Block (0,b,0) writes xi_new.
//
// Hot loop (per warp, NO block barriers): each warp owns a 128-col swath +
// private smem slice. 2-row pipeline: 8 coalesced LDG.32 (1 wavefront each)
// -> STS conflict-free -> __syncwarp -> LDS.128 -> coalesced STG.128.
// ---------------------------------------------------------------------------
__global__ void __launch_bounds__(256)
pack_kernel(const float* __restrict__ x,
            const int*   __restrict__ xi,
            const int*   __restrict__ N,
            const float* __restrict__ sep_param,
            float* __restrict__ out,
            float* __restrict__ out_xi,
            int write_xi) {
    const int b    = blockIdx.y;
    const int t    = threadIdx.x;
    const int w    = t >> 5;
    const int lane = t & 31;

    __shared__ __align__(16) float s_tile[8][2][128];  // 8 KB warp-private
    __shared__ int s_start[NMX + 1];
    __shared__ int s_end[NMX];
    __shared__ int s_src[NMX];
    __shared__ int s_n;
    __shared__ int sh_w0;

    // ---------------- meta scan (cheap, 2 block syncs) ----------------
    if (t == 0) s_n = N[b];
    __syncthreads();
    const int n = s_n;

    if (t < NMX) {
        const int s = xi[(b * NMX + t) * 2 + 0];
        const int e = xi[(b * NMX + t) * 2 + 1];
        const int valid = (t < n) ? 1 : 0;
        const int wv = valid ? max(e - s, 0) : 0;

        int sc = wv;
        #pragma unroll
        for (int off = 1; off < 32; off <<= 1) {
            int v = __shfl_up_sync(0xFFFFFFFFu, sc, off);
            if ((t & 31) >= off) sc += v;
        }
        if (t == 31) sh_w0 = sc;
        __syncwarp();
        s_end[t]   = sc;      // stash partial scan
        s_src[t]   = s;
        s_start[t] = valid;   // stash validity
    }
    __syncthreads();
    if (t < NMX) {
        const int valid = s_start[t];
        const int s = s_src[t];
        const int e = xi[(b * NMX + t) * 2 + 1];
        const int wv = valid ? max(e - s, 0) : 0;
        const int csum = s_end[t] + ((t >= 32) ? sh_w0 : 0);
        const int sn = csum - wv + t;
        const int en = csum + t;
        s_start[t] = valid ? sn : BIGV;
        s_end[t]   = en;
        if (write_xi && blockIdx.x == 0 && blockIdx.z == 0) {
            out_xi[(b * NMX + t) * 2 + 0] = valid ? (float)sn : 0.0f;
            out_xi[(b * NMX + t) * 2 + 1] = valid ? (float)en : 0.0f;
        }
    }
    if (t == 0) s_start[NMX] = BIGV;
    __syncthreads();

    // ---------------- classification: 4 stride-32 columns per lane ----
    const int   wcol = blockIdx.x * 1024 + w * 128;
    const float sep  = sep_param[0];

    int   mm[4];
    float fv[4];
    #pragma unroll
    for (int k = 0; k < 4; k++) {
        const int j = wcol + lane + 32 * k;
        int lo = 0, hi = n;
        while (lo < hi) {
            int mid = (lo + hi) >> 1;
            if (s_start[mid] <= j) lo = mid + 1; else hi = mid;
        }
        const int cur = lo - 1;
        const int s = s_start[cur];
        const int e = s_end[cur];
        int   o = -1;
        float f = 0.0f;
        if (j < e)                      o = s_src[cur] + (j - s);
        else if (j == e && cur < n - 1) f = sep;
        mm[k] = o;
        fv[k] = f;
    }

    // ---------------- hot loop: warp-private transpose pack ----------
    const int h0 = blockIdx.z * ROWS;
    const float* __restrict__ xb = x   + (size_t)b * HH * WW + (size_t)h0 * WW;
    float* __restrict__       ob = out + (size_t)b * HH * WW + (size_t)h0 * WW;

    #pragma unroll
    for (int r = 0; r < ROWS; r += 2) {
        // coalesced gather: 8 independent LDGs (2 rows x 4 chunks)
        float v[2][4];
        #pragma unroll
        for (int rr = 0; rr < 2; rr++) {
            const size_t row = (size_t)(r + rr) * WW;
            #pragma unroll
            for (int k = 0; k < 4; k++)
                v[rr][k] = (mm[k] >= 0) ? __ldg(xb + row + mm[k]) : fv[k];
        }
        // stage in warp-private smem (conflict-free STS)
        #pragma unroll
        for (int rr = 0; rr < 2; rr++)
            #pragma unroll
            for (int k = 0; k < 4; k++)
                s_tile[w][rr][lane + 32 * k] = v[rr][k];
        __syncwarp();
        // read back as float4, coalesced STG.128
        #pragma unroll
        for (int rr = 0; rr < 2; rr++) {
            const float4 f = *reinterpret_cast<const float4*>(
                &s_tile[w][rr][4 * lane]);
            __stcs(reinterpret_cast<float4*>(
                ob + (size_t)(r + rr) * WW + wcol + 4 * lane), f);
        }
        __syncwarp();   // slices reused next iteration
    }
}

// ---------------------------------------------------------------------------
extern "C" void kernel_launch(void* const* d_in, const int* in_sizes, int n_in,
                              void* d_out, int out_size) {
    const float* x   = (const float*)d_in[0];
    const int*   xi  = (const int*)  d_in[1];
    const int*   N   = (const int*)  d_in[2];
    const float* sep = (const float*)d_in[3];
    float*       out = (float*)d_out;

    const long long XN = (long long)BB * HH * WW;   // 16,777,216
    const int write_xi = ((long long)out_size > XN) ? 1 : 0;

    dim3 grid(WW / 1024, BB, HH / ROWS);
    pack_kernel<<<grid, 256>>>(x, xi, N, sep, out, out + XN, write_xi);
}